// round 1
// baseline (speedup 1.0000x reference)
#include <cuda_runtime.h>

// Problem constants
#define T_  1024
#define B_  8
#define D_  1024
#define H_  16
#define NH_ 64
#define M_  (T_ * B_)   // 8192 token rows

// ------------------------------------------------------------------
// Scratch (static __device__ globals: allocation-free per harness rules)
// ------------------------------------------------------------------
__device__ float g_q[M_ * D_];
__device__ float g_k[M_ * D_];
__device__ float g_v[M_ * D_];
__device__ float g_t[M_ * D_];
__device__ float g_x[M_ * D_];
__device__ float g_y[M_ * D_];

// ------------------------------------------------------------------
// GEMM: C[M,N] = A[M,K] @ W[K,N] + bias   (M=8192, N=K=1024)
// 64x64 block tile, BK=16, 256 threads, 4x4 per thread, fp32.
// ------------------------------------------------------------------
#define BM 64
#define BN 64
#define BK 16

__global__ __launch_bounds__(256) void gemm_bias_kernel(
    const float* __restrict__ A, const float* __restrict__ W,
    const float* __restrict__ bias, float* __restrict__ C)
{
    const int N = D_, K = D_;
    __shared__ float As[BK][BM];   // [k][m] (transposed store)
    __shared__ float Bs[BK][BN];   // [k][n]

    const int bm = blockIdx.y * BM;
    const int bn = blockIdx.x * BN;
    const int tid = threadIdx.x;
    const int tx = tid & 15;        // 0..15 -> output cols tx*4..+3
    const int ty = tid >> 4;        // 0..15 -> output rows ty*4..+3

    // A-tile load mapping: each thread loads one float4
    const int arow = tid >> 2;           // 0..63
    const int acol = (tid & 3) * 4;      // 0,4,8,12
    // B-tile load mapping
    const int brow = tid >> 4;           // 0..15
    const int bcol = (tid & 15) * 4;     // 0..60

    const float* Aptr = A + (size_t)(bm + arow) * K + acol;
    const float* Wptr = W + (size_t)brow * N + bn + bcol;

    float acc[4][4] = {};

    for (int k0 = 0; k0 < K; k0 += BK) {
        float4 av = *(const float4*)(Aptr + k0);
        float4 wv = *(const float4*)(Wptr + (size_t)k0 * N);
        As[acol + 0][arow] = av.x;
        As[acol + 1][arow] = av.y;
        As[acol + 2][arow] = av.z;
        As[acol + 3][arow] = av.w;
        *(float4*)&Bs[brow][bcol] = wv;
        __syncthreads();

#pragma unroll
        for (int kk = 0; kk < BK; kk++) {
            float4 a = *(const float4*)&As[kk][ty * 4];
            float4 b = *(const float4*)&Bs[kk][tx * 4];
            float ar[4] = {a.x, a.y, a.z, a.w};
            float br[4] = {b.x, b.y, b.z, b.w};
#pragma unroll
            for (int i = 0; i < 4; i++)
#pragma unroll
                for (int j = 0; j < 4; j++)
                    acc[i][j] += ar[i] * br[j];
        }
        __syncthreads();
    }

#pragma unroll
    for (int i = 0; i < 4; i++) {
        const size_t row = bm + ty * 4 + i;
#pragma unroll
        for (int j = 0; j < 4; j++) {
            const int col = bn + tx * 4 + j;
            C[row * N + col] = acc[i][j] + bias[col];
        }
    }
}

// ------------------------------------------------------------------
// Flash-style attention, fp32. One block handles 64 query rows for
// one (b,h). 256 threads: tid = qr*4 + cg.
//   S phase : thread computes 16 k-columns kc = cg + 4*kk (bank-friendly)
//   PV phase: thread owns output dims cg*16 .. cg*16+15
// KV layouts are [T, B, D] with head slice h*NH.
// ------------------------------------------------------------------
#define PCH 68   // smem row pitch (floats); 68*4B = 272B, 16B aligned, odd bank stride

__global__ __launch_bounds__(256) void attn_kernel(
    const float* __restrict__ Q, const float* __restrict__ K,
    const float* __restrict__ V, float* __restrict__ O, int causal)
{
    extern __shared__ float sm[];
    float* Qs  = sm;                 // [64][PCH]
    float* KVs = sm + 64 * PCH;      // [64][PCH] (K tile, then reused for V tile)
    float* Ps  = sm + 2 * 64 * PCH;  // [64][PCH]

    const int qt  = blockIdx.x;          // query tile (0..15)
    const int bh  = blockIdx.y;          // b*H + h
    const int b   = bh >> 4;
    const int h   = bh & 15;
    const int tid = threadIdx.x;
    const int qr  = tid >> 2;            // local query row 0..63
    const int cg  = tid & 3;             // column group 0..3

    // tile loader mapping (shared by Q/K/V loads): row lrow, 16 floats at lcol
    const int lrow = tid >> 2;
    const int lcol = (tid & 3) * 16;

    const float scale = 0.125f;          // 1/sqrt(64)
    const size_t head_off = (size_t)h * NH_;

    // load Q tile
    {
        const float* src = Q + ((size_t)(qt * 64 + lrow) * B_ + b) * D_ + head_off + lcol;
#pragma unroll
        for (int j = 0; j < 16; j += 4)
            *(float4*)&Qs[lrow * PCH + lcol + j] = *(const float4*)(src + j);
    }

    float m = -INFINITY, l = 0.f;
    float acc[16] = {};

    const int nkt = causal ? (qt + 1) : (T_ / 64);
    const int q_global = qt * 64 + qr;

    for (int kt = 0; kt < nkt; kt++) {
        __syncthreads();   // Qs visible (iter 0); prior-iter V reads complete
        // load K tile
        {
            const float* src = K + ((size_t)(kt * 64 + lrow) * B_ + b) * D_ + head_off + lcol;
#pragma unroll
            for (int j = 0; j < 16; j += 4)
                *(float4*)&KVs[lrow * PCH + lcol + j] = *(const float4*)(src + j);
        }
        __syncthreads();

        // S = scale * Q K^T for 16 interleaved k-columns
        float s[16];
#pragma unroll
        for (int kk = 0; kk < 16; kk++) s[kk] = 0.f;
#pragma unroll
        for (int d = 0; d < 64; d += 4) {
            const float4 qv = *(const float4*)&Qs[qr * PCH + d];
#pragma unroll
            for (int kk = 0; kk < 16; kk++) {
                const float4 kv = *(const float4*)&KVs[(cg + 4 * kk) * PCH + d];
                s[kk] += qv.x * kv.x + qv.y * kv.y + qv.z * kv.z + qv.w * kv.w;
            }
        }

        float rowmax = -INFINITY;
#pragma unroll
        for (int kk = 0; kk < 16; kk++) {
            float sv = s[kk] * scale;
            if (causal && (kt * 64 + cg + 4 * kk) > q_global) sv = -INFINITY;
            s[kk] = sv;
            rowmax = fmaxf(rowmax, sv);
        }
        rowmax = fmaxf(rowmax, __shfl_xor_sync(0xffffffffu, rowmax, 1));
        rowmax = fmaxf(rowmax, __shfl_xor_sync(0xffffffffu, rowmax, 2));

        const float mnew = fmaxf(m, rowmax);
        const float corr = __expf(m - mnew);   // m=-inf on first tile -> 0
        float psum = 0.f;
#pragma unroll
        for (int kk = 0; kk < 16; kk++) {
            const float e = __expf(s[kk] - mnew);
            s[kk] = e;
            psum += e;
        }
        psum += __shfl_xor_sync(0xffffffffu, psum, 1);
        psum += __shfl_xor_sync(0xffffffffu, psum, 2);
        l = l * corr + psum;
        m = mnew;
#pragma unroll
        for (int j = 0; j < 16; j++) acc[j] *= corr;

        // publish probabilities (conflict-free scalar stores)
#pragma unroll
        for (int kk = 0; kk < 16; kk++)
            Ps[qr * PCH + cg + 4 * kk] = s[kk];
        __syncthreads();   // Ps visible; all K-tile reads complete

        // load V tile (overwrites KVs)
        {
            const float* src = V + ((size_t)(kt * 64 + lrow) * B_ + b) * D_ + head_off + lcol;
#pragma unroll
            for (int j = 0; j < 16; j += 4)
                *(float4*)&KVs[lrow * PCH + lcol + j] = *(const float4*)(src + j);
        }
        __syncthreads();

        // acc += P @ V   (thread: dims cg*16 .. +15)
#pragma unroll 4
        for (int k = 0; k < 64; k++) {
            const float pv = Ps[qr * PCH + k];
#pragma unroll
            for (int j = 0; j < 16; j += 4) {
                const float4 vv = *(const float4*)&KVs[k * PCH + cg * 16 + j];
                acc[j + 0] += pv * vv.x;
                acc[j + 1] += pv * vv.y;
                acc[j + 2] += pv * vv.z;
                acc[j + 3] += pv * vv.w;
            }
        }
    }

    const float inv = 1.f / l;
    float* dst = O + ((size_t)q_global * B_ + b) * D_ + head_off + cg * 16;
#pragma unroll
    for (int j = 0; j < 16; j += 4) {
        float4 o = make_float4(acc[j] * inv, acc[j + 1] * inv,
                               acc[j + 2] * inv, acc[j + 3] * inv);
        *(float4*)(dst + j) = o;
    }
}

#define ATTN_SMEM (3 * 64 * PCH * 4)

// ------------------------------------------------------------------
// Fused residual add + LayerNorm over D=1024. One block per row.
// ------------------------------------------------------------------
__global__ __launch_bounds__(256) void add_ln_kernel(
    const float* __restrict__ a, const float* __restrict__ res,
    const float* __restrict__ g, const float* __restrict__ be,
    float* __restrict__ out)
{
    const size_t row = blockIdx.x;
    const float* pa = a + row * D_;
    const float* pr = res + row * D_;
    const int tid = threadIdx.x;

    float v[4];
    float s = 0.f, ss = 0.f;
#pragma unroll
    for (int i = 0; i < 4; i++) {
        const int c = tid + i * 256;
        const float x = pa[c] + pr[c];
        v[i] = x;
        s += x;
        ss += x * x;
    }
    __shared__ float red[2][8];
#pragma unroll
    for (int o = 16; o; o >>= 1) {
        s  += __shfl_xor_sync(0xffffffffu, s, o);
        ss += __shfl_xor_sync(0xffffffffu, ss, o);
    }
    const int w = tid >> 5;
    if ((tid & 31) == 0) { red[0][w] = s; red[1][w] = ss; }
    __syncthreads();
    if (tid < 32) {
        s  = (tid < 8) ? red[0][tid] : 0.f;
        ss = (tid < 8) ? red[1][tid] : 0.f;
#pragma unroll
        for (int o = 4; o; o >>= 1) {
            s  += __shfl_xor_sync(0xffffffffu, s, o);
            ss += __shfl_xor_sync(0xffffffffu, ss, o);
        }
        if (tid == 0) { red[0][0] = s; red[1][0] = ss; }
    }
    __syncthreads();
    s = red[0][0]; ss = red[1][0];

    const float mean = s * (1.f / 1024.f);
    const float var  = ss * (1.f / 1024.f) - mean * mean;
    const float rstd = rsqrtf(var + 1e-5f);
#pragma unroll
    for (int i = 0; i < 4; i++) {
        const int c = tid + i * 256;
        out[row * D_ + c] = (v[i] - mean) * rstd * g[c] + be[c];
    }
}

// ------------------------------------------------------------------
// Orchestration
// ------------------------------------------------------------------
extern "C" void kernel_launch(void* const* d_in, const int* in_sizes, int n_in,
                              void* d_out, int out_size)
{
    const float* enc = (const float*)d_in[0];
    const float* dec = (const float*)d_in[1];
    const float* Wq1 = (const float*)d_in[2];  const float* bq1 = (const float*)d_in[3];
    const float* Wk1 = (const float*)d_in[4];  const float* bk1 = (const float*)d_in[5];
    const float* Wv1 = (const float*)d_in[6];  const float* bv1 = (const float*)d_in[7];
    const float* Wq2 = (const float*)d_in[8];  const float* bq2 = (const float*)d_in[9];
    const float* Wk2 = (const float*)d_in[10]; const float* bk2 = (const float*)d_in[11];
    const float* Wv2 = (const float*)d_in[12]; const float* bv2 = (const float*)d_in[13];
    const float* Wl  = (const float*)d_in[14]; const float* bl  = (const float*)d_in[15];
    const float* g1  = (const float*)d_in[16]; const float* be1 = (const float*)d_in[17];
    const float* g2  = (const float*)d_in[18]; const float* be2 = (const float*)d_in[19];
    const float* g3  = (const float*)d_in[20]; const float* be3 = (const float*)d_in[21];
    float* out = (float*)d_out;

    float *q, *k, *v, *t, *x, *y;
    cudaGetSymbolAddress((void**)&q, g_q);
    cudaGetSymbolAddress((void**)&k, g_k);
    cudaGetSymbolAddress((void**)&v, g_v);
    cudaGetSymbolAddress((void**)&t, g_t);
    cudaGetSymbolAddress((void**)&x, g_x);
    cudaGetSymbolAddress((void**)&y, g_y);

    cudaFuncSetAttribute(attn_kernel,
                         cudaFuncAttributeMaxDynamicSharedMemorySize, ATTN_SMEM);

    const dim3 gg(D_ / BN, M_ / BM);        // (16, 128)
    const dim3 ga(T_ / 64, B_ * H_);        // (16, 128)

    // --- self-attention block ---
    gemm_bias_kernel<<<gg, 256>>>(dec, Wq1, bq1, q);
    gemm_bias_kernel<<<gg, 256>>>(dec, Wk1, bk1, k);
    gemm_bias_kernel<<<gg, 256>>>(dec, Wv1, bv1, v);
    attn_kernel<<<ga, 256, ATTN_SMEM>>>(q, k, v, t, 1);
    add_ln_kernel<<<M_, 256>>>(t, dec, g1, be1, x);

    // --- cross-attention block ---
    gemm_bias_kernel<<<gg, 256>>>(x,   Wq2, bq2, q);
    gemm_bias_kernel<<<gg, 256>>>(enc, Wk2, bk2, k);
    gemm_bias_kernel<<<gg, 256>>>(enc, Wv2, bv2, v);
    attn_kernel<<<ga, 256, ATTN_SMEM>>>(q, k, v, t, 0);
    add_ln_kernel<<<M_, 256>>>(t, x, g2, be2, y);

    // --- position-wise linear + final LN ---
    gemm_bias_kernel<<<gg, 256>>>(y, Wl, bl, t);
    add_ln_kernel<<<M_, 256>>>(t, y, g3, be3, out);
}

// round 3
// speedup vs baseline: 1.4382x; 1.4382x over previous
#include <cuda_runtime.h>
#include <cstdint>

// Problem constants
#define T_  1024
#define B_  8
#define D_  1024
#define H_  16
#define NH_ 64
#define M_  (T_ * B_)   // 8192 token rows

// ------------------------------------------------------------------
// Scratch (static __device__ globals: allocation-free per harness rules)
// ------------------------------------------------------------------
__device__ float g_q[M_ * D_];
__device__ float g_k[M_ * D_];
__device__ float g_v[M_ * D_];
__device__ float g_t[M_ * D_];
__device__ float g_x[M_ * D_];
__device__ float g_y[M_ * D_];

// ------------------------------------------------------------------
// tf32 helpers (baseline PTX, sm_80+ features -> compiles at compute_103)
// ------------------------------------------------------------------
__device__ __forceinline__ uint32_t to_tf32(float x) {
    uint32_t r;
    asm("cvt.rna.tf32.f32 %0, %1;" : "=r"(r) : "f"(x));
    return r;
}

__device__ __forceinline__ void mma1688(float* c, const uint32_t* a,
                                        const uint32_t* b) {
    asm volatile(
        "mma.sync.aligned.m16n8k8.row.col.f32.tf32.tf32.f32 "
        "{%0,%1,%2,%3}, {%4,%5,%6,%7}, {%8,%9}, {%0,%1,%2,%3};\n"
        : "+f"(c[0]), "+f"(c[1]), "+f"(c[2]), "+f"(c[3])
        : "r"(a[0]), "r"(a[1]), "r"(a[2]), "r"(a[3]),
          "r"(b[0]), "r"(b[1]));
}

// ==================================================================
// tf32 mma.sync GEMM: C[8192,1024] = A @ W + bias
// CTA tile 128x128, BK=32. 8 warps in 4(m) x 2(n); warp tile 32x64.
// Smem pitch 36 floats: fragment loads are bank-conflict-free
// (bank = (4g + t + const) mod 32, distinct per lane).
// ==================================================================
#define GPITCH 36

__global__ __launch_bounds__(256) void gemm_mma_kernel(
    const float* __restrict__ A, const float* __restrict__ W,
    const float* __restrict__ bias, float* __restrict__ C)
{
    __shared__ __align__(16) float As[128][GPITCH];   // [m][k]
    __shared__ __align__(16) float Bs[128][GPITCH];   // [n][k]  (= W^T tile)

    const int tid = threadIdx.x;
    const int wid = tid >> 5;
    const int lid = tid & 31;
    const int g   = lid >> 2;      // 0..7
    const int t   = lid & 3;       // 0..3

    const int warp_m = wid >> 1;   // 0..3
    const int warp_n = wid & 1;    // 0..1

    const int bn = blockIdx.x * 128;
    const int bm = blockIdx.y * 128;

    // loader mappings
    const int a_row0 = tid >> 3;          // +i*32
    const int a_c    = (tid & 7) * 4;
    const int b_n    = tid & 127;
    const int b_g0   = tid >> 7;          // 0..1

    float acc[2][8][4];
#pragma unroll
    for (int mt = 0; mt < 2; mt++)
#pragma unroll
        for (int nt = 0; nt < 8; nt++)
#pragma unroll
            for (int r = 0; r < 4; r++) acc[mt][nt][r] = 0.f;

    for (int kb = 0; kb < 32; kb++) {
        const int k0 = kb * 32;

        // ---- A tile: [128 m][32 k], coalesced float4 reads ----
#pragma unroll
        for (int i = 0; i < 4; i++) {
            const int row = a_row0 + i * 32;
            const float4 v = *(const float4*)(A + (size_t)(bm + row) * 1024
                                              + k0 + a_c);
            uint4 tv;
            tv.x = to_tf32(v.x); tv.y = to_tf32(v.y);
            tv.z = to_tf32(v.z); tv.w = to_tf32(v.w);
            *(uint4*)&As[row][a_c] = tv;
        }
        // ---- B tile: Bs[n][k] = W[k][n], 4 coalesced row-segments ----
#pragma unroll
        for (int p = 0; p < 4; p++) {
            const int kk0 = (b_g0 + p * 2) * 4;
            const float* wp = W + (size_t)(k0 + kk0) * 1024 + bn + b_n;
            uint4 tv;
            tv.x = to_tf32(wp[0]);
            tv.y = to_tf32(wp[1024]);
            tv.z = to_tf32(wp[2048]);
            tv.w = to_tf32(wp[3072]);
            *(uint4*)&Bs[b_n][kk0] = tv;
        }
        __syncthreads();

        // ---- compute: 4 k-steps x (2 m-tiles x 8 n-tiles) mma ----
#pragma unroll
        for (int ks = 0; ks < 4; ks++) {
            uint32_t af[2][4];
#pragma unroll
            for (int mt = 0; mt < 2; mt++) {
                const uint32_t* ap =
                    (const uint32_t*)&As[warp_m * 32 + mt * 16 + g][ks * 8 + t];
                af[mt][0] = ap[0];
                af[mt][1] = ap[8 * GPITCH];
                af[mt][2] = ap[4];
                af[mt][3] = ap[8 * GPITCH + 4];
            }
#pragma unroll
            for (int nt = 0; nt < 8; nt++) {
                const uint32_t* bp =
                    (const uint32_t*)&Bs[warp_n * 64 + nt * 8 + g][ks * 8 + t];
                uint32_t bf[2] = {bp[0], bp[4]};
                mma1688(acc[0][nt], af[0], bf);
                mma1688(acc[1][nt], af[1], bf);
            }
        }
        __syncthreads();
    }

    // ---- epilogue: bias + store (float2 per fragment row) ----
#pragma unroll
    for (int nt = 0; nt < 8; nt++) {
        const int col = bn + warp_n * 64 + nt * 8 + 2 * t;
        const float2 bv = *(const float2*)(bias + col);
#pragma unroll
        for (int mt = 0; mt < 2; mt++) {
            const int row0 = bm + warp_m * 32 + mt * 16 + g;
            float2 v0 = make_float2(acc[mt][nt][0] + bv.x,
                                    acc[mt][nt][1] + bv.y);
            float2 v1 = make_float2(acc[mt][nt][2] + bv.x,
                                    acc[mt][nt][3] + bv.y);
            *(float2*)(C + (size_t)row0 * 1024 + col) = v0;
            *(float2*)(C + (size_t)(row0 + 8) * 1024 + col) = v1;
        }
    }
}

// ------------------------------------------------------------------
// Flash-style attention, fp32 (unchanged from R1).
// ------------------------------------------------------------------
#define PCH 68

__global__ __launch_bounds__(256) void attn_kernel(
    const float* __restrict__ Q, const float* __restrict__ K,
    const float* __restrict__ V, float* __restrict__ O, int causal)
{
    extern __shared__ float sm[];
    float* Qs  = sm;
    float* KVs = sm + 64 * PCH;
    float* Ps  = sm + 2 * 64 * PCH;

    const int qt  = blockIdx.x;
    const int bh  = blockIdx.y;
    const int b   = bh >> 4;
    const int h   = bh & 15;
    const int tid = threadIdx.x;
    const int qr  = tid >> 2;
    const int cg  = tid & 3;

    const int lrow = tid >> 2;
    const int lcol = (tid & 3) * 16;

    const float scale = 0.125f;
    const size_t head_off = (size_t)h * NH_;

    {
        const float* src = Q + ((size_t)(qt * 64 + lrow) * B_ + b) * D_ + head_off + lcol;
#pragma unroll
        for (int j = 0; j < 16; j += 4)
            *(float4*)&Qs[lrow * PCH + lcol + j] = *(const float4*)(src + j);
    }

    float m = -INFINITY, l = 0.f;
    float acc[16] = {};

    const int nkt = causal ? (qt + 1) : (T_ / 64);
    const int q_global = qt * 64 + qr;

    for (int kt = 0; kt < nkt; kt++) {
        __syncthreads();
        {
            const float* src = K + ((size_t)(kt * 64 + lrow) * B_ + b) * D_ + head_off + lcol;
#pragma unroll
            for (int j = 0; j < 16; j += 4)
                *(float4*)&KVs[lrow * PCH + lcol + j] = *(const float4*)(src + j);
        }
        __syncthreads();

        float s[16];
#pragma unroll
        for (int kk = 0; kk < 16; kk++) s[kk] = 0.f;
#pragma unroll
        for (int d = 0; d < 64; d += 4) {
            const float4 qv = *(const float4*)&Qs[qr * PCH + d];
#pragma unroll
            for (int kk = 0; kk < 16; kk++) {
                const float4 kv = *(const float4*)&KVs[(cg + 4 * kk) * PCH + d];
                s[kk] += qv.x * kv.x + qv.y * kv.y + qv.z * kv.z + qv.w * kv.w;
            }
        }

        float rowmax = -INFINITY;
#pragma unroll
        for (int kk = 0; kk < 16; kk++) {
            float sv = s[kk] * scale;
            if (causal && (kt * 64 + cg + 4 * kk) > q_global) sv = -INFINITY;
            s[kk] = sv;
            rowmax = fmaxf(rowmax, sv);
        }
        rowmax = fmaxf(rowmax, __shfl_xor_sync(0xffffffffu, rowmax, 1));
        rowmax = fmaxf(rowmax, __shfl_xor_sync(0xffffffffu, rowmax, 2));

        const float mnew = fmaxf(m, rowmax);
        const float corr = __expf(m - mnew);
        float psum = 0.f;
#pragma unroll
        for (int kk = 0; kk < 16; kk++) {
            const float e = __expf(s[kk] - mnew);
            s[kk] = e;
            psum += e;
        }
        psum += __shfl_xor_sync(0xffffffffu, psum, 1);
        psum += __shfl_xor_sync(0xffffffffu, psum, 2);
        l = l * corr + psum;
        m = mnew;
#pragma unroll
        for (int j = 0; j < 16; j++) acc[j] *= corr;

#pragma unroll
        for (int kk = 0; kk < 16; kk++)
            Ps[qr * PCH + cg + 4 * kk] = s[kk];
        __syncthreads();

        {
            const float* src = V + ((size_t)(kt * 64 + lrow) * B_ + b) * D_ + head_off + lcol;
#pragma unroll
            for (int j = 0; j < 16; j += 4)
                *(float4*)&KVs[lrow * PCH + lcol + j] = *(const float4*)(src + j);
        }
        __syncthreads();

#pragma unroll 4
        for (int k = 0; k < 64; k++) {
            const float pv = Ps[qr * PCH + k];
#pragma unroll
            for (int j = 0; j < 16; j += 4) {
                const float4 vv = *(const float4*)&KVs[k * PCH + cg * 16 + j];
                acc[j + 0] += pv * vv.x;
                acc[j + 1] += pv * vv.y;
                acc[j + 2] += pv * vv.z;
                acc[j + 3] += pv * vv.w;
            }
        }
    }

    const float inv = 1.f / l;
    float* dst = O + ((size_t)q_global * B_ + b) * D_ + head_off + cg * 16;
#pragma unroll
    for (int j = 0; j < 16; j += 4) {
        float4 o = make_float4(acc[j] * inv, acc[j + 1] * inv,
                               acc[j + 2] * inv, acc[j + 3] * inv);
        *(float4*)(dst + j) = o;
    }
}

#define ATTN_SMEM (3 * 64 * PCH * 4)

// ------------------------------------------------------------------
// Fused residual add + LayerNorm over D=1024 (unchanged).
// ------------------------------------------------------------------
__global__ __launch_bounds__(256) void add_ln_kernel(
    const float* __restrict__ a, const float* __restrict__ res,
    const float* __restrict__ g, const float* __restrict__ be,
    float* __restrict__ out)
{
    const size_t row = blockIdx.x;
    const float* pa = a + row * D_;
    const float* pr = res + row * D_;
    const int tid = threadIdx.x;

    float v[4];
    float s = 0.f, ss = 0.f;
#pragma unroll
    for (int i = 0; i < 4; i++) {
        const int c = tid + i * 256;
        const float x = pa[c] + pr[c];
        v[i] = x;
        s += x;
        ss += x * x;
    }
    __shared__ float red[2][8];
#pragma unroll
    for (int o = 16; o; o >>= 1) {
        s  += __shfl_xor_sync(0xffffffffu, s, o);
        ss += __shfl_xor_sync(0xffffffffu, ss, o);
    }
    const int w = tid >> 5;
    if ((tid & 31) == 0) { red[0][w] = s; red[1][w] = ss; }
    __syncthreads();
    if (tid < 32) {
        s  = (tid < 8) ? red[0][tid] : 0.f;
        ss = (tid < 8) ? red[1][tid] : 0.f;
#pragma unroll
        for (int o = 4; o; o >>= 1) {
            s  += __shfl_xor_sync(0xffffffffu, s, o);
            ss += __shfl_xor_sync(0xffffffffu, ss, o);
        }
        if (tid == 0) { red[0][0] = s; red[1][0] = ss; }
    }
    __syncthreads();
    s = red[0][0]; ss = red[1][0];

    const float mean = s * (1.f / 1024.f);
    const float var  = ss * (1.f / 1024.f) - mean * mean;
    const float rstd = rsqrtf(var + 1e-5f);
#pragma unroll
    for (int i = 0; i < 4; i++) {
        const int c = tid + i * 256;
        out[row * D_ + c] = (v[i] - mean) * rstd * g[c] + be[c];
    }
}

// ------------------------------------------------------------------
// Orchestration
// ------------------------------------------------------------------
extern "C" void kernel_launch(void* const* d_in, const int* in_sizes, int n_in,
                              void* d_out, int out_size)
{
    const float* enc = (const float*)d_in[0];
    const float* dec = (const float*)d_in[1];
    const float* Wq1 = (const float*)d_in[2];  const float* bq1 = (const float*)d_in[3];
    const float* Wk1 = (const float*)d_in[4];  const float* bk1 = (const float*)d_in[5];
    const float* Wv1 = (const float*)d_in[6];  const float* bv1 = (const float*)d_in[7];
    const float* Wq2 = (const float*)d_in[8];  const float* bq2 = (const float*)d_in[9];
    const float* Wk2 = (const float*)d_in[10]; const float* bk2 = (const float*)d_in[11];
    const float* Wv2 = (const float*)d_in[12]; const float* bv2 = (const float*)d_in[13];
    const float* Wl  = (const float*)d_in[14]; const float* bl  = (const float*)d_in[15];
    const float* g1  = (const float*)d_in[16]; const float* be1 = (const float*)d_in[17];
    const float* g2  = (const float*)d_in[18]; const float* be2 = (const float*)d_in[19];
    const float* g3  = (const float*)d_in[20]; const float* be3 = (const float*)d_in[21];
    float* out = (float*)d_out;

    float *q, *k, *v, *t, *x, *y;
    cudaGetSymbolAddress((void**)&q, g_q);
    cudaGetSymbolAddress((void**)&k, g_k);
    cudaGetSymbolAddress((void**)&v, g_v);
    cudaGetSymbolAddress((void**)&t, g_t);
    cudaGetSymbolAddress((void**)&x, g_x);
    cudaGetSymbolAddress((void**)&y, g_y);

    cudaFuncSetAttribute(attn_kernel,
                         cudaFuncAttributeMaxDynamicSharedMemorySize, ATTN_SMEM);

    const dim3 gg(D_ / 128, M_ / 128);      // (8, 64)
    const dim3 ga(T_ / 64, B_ * H_);        // (16, 128)

    // --- self-attention block ---
    gemm_mma_kernel<<<gg, 256>>>(dec, Wq1, bq1, q);
    gemm_mma_kernel<<<gg, 256>>>(dec, Wk1, bk1, k);
    gemm_mma_kernel<<<gg, 256>>>(dec, Wv1, bv1, v);
    attn_kernel<<<ga, 256, ATTN_SMEM>>>(q, k, v, t, 1);
    add_ln_kernel<<<M_, 256>>>(t, dec, g1, be1, x);

    // --- cross-attention block ---
    gemm_mma_kernel<<<gg, 256>>>(x,   Wq2, bq2, q);
    gemm_mma_kernel<<<gg, 256>>>(enc, Wk2, bk2, k);
    gemm_mma_kernel<<<gg, 256>>>(enc, Wv2, bv2, v);
    attn_kernel<<<ga, 256, ATTN_SMEM>>>(q, k, v, t, 0);
    add_ln_kernel<<<M_, 256>>>(t, x, g2, be2, y);

    // --- position-wise linear + final LN ---
    gemm_mma_kernel<<<gg, 256>>>(y, Wl, bl, t);
    add_ln_kernel<<<M_, 256>>>(t, y, g3, be3, out);
}

// round 5
// speedup vs baseline: 5.0742x; 3.5281x over previous
#include <cuda_runtime.h>
#include <cstdint>

// Problem constants
#define T_  1024
#define B_  8
#define D_  1024
#define H_  16
#define NH_ 64
#define M_  (T_ * B_)   // 8192 token rows

// ------------------------------------------------------------------
// Scratch (static __device__ globals: allocation-free per harness rules)
// ------------------------------------------------------------------
__device__ float g_q[M_ * D_];
__device__ float g_k[M_ * D_];
__device__ float g_v[M_ * D_];
__device__ float g_t[M_ * D_];
__device__ float g_x[M_ * D_];
__device__ float g_y[M_ * D_];

// ------------------------------------------------------------------
// tf32 helpers
// ------------------------------------------------------------------
__device__ __forceinline__ uint32_t to_tf32(float x) {
    uint32_t r;
    asm("cvt.rna.tf32.f32 %0, %1;" : "=r"(r) : "f"(x));
    return r;
}

__device__ __forceinline__ void mma1688(float* c, const uint32_t* a,
                                        const uint32_t* b) {
    asm volatile(
        "mma.sync.aligned.m16n8k8.row.col.f32.tf32.tf32.f32 "
        "{%0,%1,%2,%3}, {%4,%5,%6,%7}, {%8,%9}, {%0,%1,%2,%3};\n"
        : "+f"(c[0]), "+f"(c[1]), "+f"(c[2]), "+f"(c[3])
        : "r"(a[0]), "r"(a[1]), "r"(a[2]), "r"(a[3]),
          "r"(b[0]), "r"(b[1]));
}

// ==================================================================
// tf32 mma.sync GEMM: C[8192,1024] = A @ W + bias  (unchanged, passing)
// ==================================================================
#define GPITCH 36

__global__ __launch_bounds__(256) void gemm_mma_kernel(
    const float* __restrict__ A, const float* __restrict__ W,
    const float* __restrict__ bias, float* __restrict__ C)
{
    __shared__ __align__(16) float As[128][GPITCH];   // [m][k]
    __shared__ __align__(16) float Bs[128][GPITCH];   // [n][k]  (= W^T tile)

    const int tid = threadIdx.x;
    const int wid = tid >> 5;
    const int lid = tid & 31;
    const int g   = lid >> 2;
    const int t   = lid & 3;

    const int warp_m = wid >> 1;
    const int warp_n = wid & 1;

    const int bn = blockIdx.x * 128;
    const int bm = blockIdx.y * 128;

    const int a_row0 = tid >> 3;
    const int a_c    = (tid & 7) * 4;
    const int b_n    = tid & 127;
    const int b_g0   = tid >> 7;

    float acc[2][8][4];
#pragma unroll
    for (int mt = 0; mt < 2; mt++)
#pragma unroll
        for (int nt = 0; nt < 8; nt++)
#pragma unroll
            for (int r = 0; r < 4; r++) acc[mt][nt][r] = 0.f;

    for (int kb = 0; kb < 32; kb++) {
        const int k0 = kb * 32;

#pragma unroll
        for (int i = 0; i < 4; i++) {
            const int row = a_row0 + i * 32;
            const float4 v = *(const float4*)(A + (size_t)(bm + row) * 1024
                                              + k0 + a_c);
            uint4 tv;
            tv.x = to_tf32(v.x); tv.y = to_tf32(v.y);
            tv.z = to_tf32(v.z); tv.w = to_tf32(v.w);
            *(uint4*)&As[row][a_c] = tv;
        }
#pragma unroll
        for (int p = 0; p < 4; p++) {
            const int kk0 = (b_g0 + p * 2) * 4;
            const float* wp = W + (size_t)(k0 + kk0) * 1024 + bn + b_n;
            uint4 tv;
            tv.x = to_tf32(wp[0]);
            tv.y = to_tf32(wp[1024]);
            tv.z = to_tf32(wp[2048]);
            tv.w = to_tf32(wp[3072]);
            *(uint4*)&Bs[b_n][kk0] = tv;
        }
        __syncthreads();

#pragma unroll
        for (int ks = 0; ks < 4; ks++) {
            uint32_t af[2][4];
#pragma unroll
            for (int mt = 0; mt < 2; mt++) {
                const uint32_t* ap =
                    (const uint32_t*)&As[warp_m * 32 + mt * 16 + g][ks * 8 + t];
                af[mt][0] = ap[0];
                af[mt][1] = ap[8 * GPITCH];
                af[mt][2] = ap[4];
                af[mt][3] = ap[8 * GPITCH + 4];
            }
#pragma unroll
            for (int nt = 0; nt < 8; nt++) {
                const uint32_t* bp =
                    (const uint32_t*)&Bs[warp_n * 64 + nt * 8 + g][ks * 8 + t];
                uint32_t bf[2] = {bp[0], bp[4]};
                mma1688(acc[0][nt], af[0], bf);
                mma1688(acc[1][nt], af[1], bf);
            }
        }
        __syncthreads();
    }

#pragma unroll
    for (int nt = 0; nt < 8; nt++) {
        const int col = bn + warp_n * 64 + nt * 8 + 2 * t;
        const float2 bv = *(const float2*)(bias + col);
#pragma unroll
        for (int mt = 0; mt < 2; mt++) {
            const int row0 = bm + warp_m * 32 + mt * 16 + g;
            float2 v0 = make_float2(acc[mt][nt][0] + bv.x,
                                    acc[mt][nt][1] + bv.y);
            float2 v1 = make_float2(acc[mt][nt][2] + bv.x,
                                    acc[mt][nt][3] + bv.y);
            *(float2*)(C + (size_t)row0 * 1024 + col) = v0;
            *(float2*)(C + (size_t)(row0 + 8) * 1024 + col) = v1;
        }
    }
}

// ==================================================================
// FlashAttention-2-style tf32 mma.sync attention.
// Block: 128 q-rows for one (b,h). 8 warps; each warp owns 16 q-rows
// and the full 64-key / 64-d width (softmax reductions stay in-warp).
// Tiles are 64 wide -> pitches must be >= 64:
//   Qs/Ks/Ps pitch 68 (68%32=4): row-major frag bank = 4g+t, distinct.
//   Vs pitch 72 (72%32=8): col-major frag bank = 8t+g, distinct.
// ==================================================================
#define QP 68
#define KP 68
#define VP 72
#define PP 68
#define ATTN_SMEM ((128 * QP + 64 * KP + 64 * VP + 128 * PP) * 4)  // 105472 B

__global__ __launch_bounds__(256, 2) void attn_mma_kernel(
    const float* __restrict__ Q, const float* __restrict__ K,
    const float* __restrict__ V, float* __restrict__ O, int causal)
{
    extern __shared__ float sm[];
    float* Qs = sm;                      // [128][QP]
    float* Ks = Qs + 128 * QP;           // [64][KP]
    float* Vs = Ks + 64 * KP;            // [64][VP]
    float* Ps = Vs + 64 * VP;            // [128][PP]

    const int qt  = blockIdx.x;          // q tile (0..7), 128 rows each
    const int bh  = blockIdx.y;
    const int b   = bh >> 4;
    const int h   = bh & 15;
    const int tid = threadIdx.x;
    const int wid = tid >> 5;
    const int lid = tid & 31;
    const int g   = lid >> 2;            // 0..7
    const int t   = lid & 3;             // 0..3

    const size_t head_off = (size_t)h * NH_;
    const int lr = tid >> 2;             // 0..63 loader row
    const int lc = (tid & 3) * 16;       // loader col (16 floats)

    // ---- load Q tile 128x64 -> Qs (tf32) ----
#pragma unroll
    for (int half = 0; half < 2; half++) {
        const int row = lr + half * 64;
        const float* src = Q + ((size_t)(qt * 128 + row) * B_ + b) * D_
                             + head_off + lc;
#pragma unroll
        for (int j = 0; j < 16; j += 4) {
            const float4 v = *(const float4*)(src + j);
            uint4 tv;
            tv.x = to_tf32(v.x); tv.y = to_tf32(v.y);
            tv.z = to_tf32(v.z); tv.w = to_tf32(v.w);
            *(uint4*)&Qs[row * QP + lc + j] = tv;
        }
    }

    float m0 = -INFINITY, m1 = -INFINITY, l0 = 0.f, l1 = 0.f;
    float o[8][4];
#pragma unroll
    for (int nt = 0; nt < 8; nt++)
#pragma unroll
        for (int r = 0; r < 4; r++) o[nt][r] = 0.f;

    const int nkt = causal ? (2 * qt + 2) : (T_ / 64);
    const int q_r0 = qt * 128 + wid * 16 + g;   // global q row (and +8)
    const int qrow_s = wid * 16 + g;            // smem q row

    for (int kt = 0; kt < nkt; kt++) {
        __syncthreads();   // prior-tile reads of Ks/Vs complete (and Qs on iter 0)

        // ---- load K,V tiles (64x64 each) -> smem (tf32) ----
        {
            const float* ksrc = K + ((size_t)(kt * 64 + lr) * B_ + b) * D_
                                  + head_off + lc;
            const float* vsrc = V + ((size_t)(kt * 64 + lr) * B_ + b) * D_
                                  + head_off + lc;
#pragma unroll
            for (int j = 0; j < 16; j += 4) {
                const float4 kv = *(const float4*)(ksrc + j);
                uint4 tk;
                tk.x = to_tf32(kv.x); tk.y = to_tf32(kv.y);
                tk.z = to_tf32(kv.z); tk.w = to_tf32(kv.w);
                *(uint4*)&Ks[lr * KP + lc + j] = tk;
                const float4 vv = *(const float4*)(vsrc + j);
                uint4 tv;
                tv.x = to_tf32(vv.x); tv.y = to_tf32(vv.y);
                tv.z = to_tf32(vv.z); tv.w = to_tf32(vv.w);
                *(uint4*)&Vs[lr * VP + lc + j] = tv;
            }
        }
        __syncthreads();

        // ---- S = Q K^T (warp: 16 q x 64 key) ----
        float sacc[8][4];
#pragma unroll
        for (int nt = 0; nt < 8; nt++)
#pragma unroll
            for (int r = 0; r < 4; r++) sacc[nt][r] = 0.f;

#pragma unroll
        for (int ks = 0; ks < 8; ks++) {
            uint32_t af[4];
            const uint32_t* ap = (const uint32_t*)&Qs[qrow_s * QP + ks * 8 + t];
            af[0] = ap[0];
            af[1] = ap[8 * QP];
            af[2] = ap[4];
            af[3] = ap[8 * QP + 4];
#pragma unroll
            for (int nt = 0; nt < 8; nt++) {
                const uint32_t* bp =
                    (const uint32_t*)&Ks[(nt * 8 + g) * KP + ks * 8 + t];
                uint32_t bf[2] = {bp[0], bp[4]};
                mma1688(sacc[nt], af, bf);
            }
        }

        // ---- scale + causal mask + online softmax ----
        const float scale = 0.125f;
        const bool domask = causal && (kt >= 2 * qt);
        float rmax0 = -INFINITY, rmax1 = -INFINITY;
#pragma unroll
        for (int nt = 0; nt < 8; nt++) {
            float c0 = sacc[nt][0] * scale;
            float c1 = sacc[nt][1] * scale;
            float c2 = sacc[nt][2] * scale;
            float c3 = sacc[nt][3] * scale;
            if (domask) {
                const int col = kt * 64 + nt * 8 + 2 * t;
                if (col     > q_r0)     c0 = -INFINITY;
                if (col + 1 > q_r0)     c1 = -INFINITY;
                if (col     > q_r0 + 8) c2 = -INFINITY;
                if (col + 1 > q_r0 + 8) c3 = -INFINITY;
            }
            sacc[nt][0] = c0; sacc[nt][1] = c1;
            sacc[nt][2] = c2; sacc[nt][3] = c3;
            rmax0 = fmaxf(rmax0, fmaxf(c0, c1));
            rmax1 = fmaxf(rmax1, fmaxf(c2, c3));
        }
        rmax0 = fmaxf(rmax0, __shfl_xor_sync(0xffffffffu, rmax0, 1));
        rmax0 = fmaxf(rmax0, __shfl_xor_sync(0xffffffffu, rmax0, 2));
        rmax1 = fmaxf(rmax1, __shfl_xor_sync(0xffffffffu, rmax1, 1));
        rmax1 = fmaxf(rmax1, __shfl_xor_sync(0xffffffffu, rmax1, 2));

        const float mn0 = fmaxf(m0, rmax0);
        const float mn1 = fmaxf(m1, rmax1);
        const float corr0 = __expf(m0 - mn0);
        const float corr1 = __expf(m1 - mn1);

        float ps0 = 0.f, ps1 = 0.f;
#pragma unroll
        for (int nt = 0; nt < 8; nt++) {
            const float p0 = __expf(sacc[nt][0] - mn0);
            const float p1 = __expf(sacc[nt][1] - mn0);
            const float p2 = __expf(sacc[nt][2] - mn1);
            const float p3 = __expf(sacc[nt][3] - mn1);
            ps0 += p0 + p1;
            ps1 += p2 + p3;
            float2 w0, w1;
            w0.x = __uint_as_float(to_tf32(p0));
            w0.y = __uint_as_float(to_tf32(p1));
            w1.x = __uint_as_float(to_tf32(p2));
            w1.y = __uint_as_float(to_tf32(p3));
            *(float2*)&Ps[qrow_s * PP + nt * 8 + 2 * t] = w0;
            *(float2*)&Ps[(qrow_s + 8) * PP + nt * 8 + 2 * t] = w1;
        }
        ps0 += __shfl_xor_sync(0xffffffffu, ps0, 1);
        ps0 += __shfl_xor_sync(0xffffffffu, ps0, 2);
        ps1 += __shfl_xor_sync(0xffffffffu, ps1, 1);
        ps1 += __shfl_xor_sync(0xffffffffu, ps1, 2);

        l0 = l0 * corr0 + ps0;
        l1 = l1 * corr1 + ps1;
        m0 = mn0;
        m1 = mn1;
#pragma unroll
        for (int nt = 0; nt < 8; nt++) {
            o[nt][0] *= corr0; o[nt][1] *= corr0;
            o[nt][2] *= corr1; o[nt][3] *= corr1;
        }

        __syncwarp();   // order Ps stores before fragment loads (warp-private rows)

        // ---- O += P V (contraction over 64 keys) ----
#pragma unroll
        for (int ks = 0; ks < 8; ks++) {
            uint32_t af[4];
            const uint32_t* ap = (const uint32_t*)&Ps[qrow_s * PP + ks * 8 + t];
            af[0] = ap[0];
            af[1] = ap[8 * PP];
            af[2] = ap[4];
            af[3] = ap[8 * PP + 4];
#pragma unroll
            for (int nt = 0; nt < 8; nt++) {
                uint32_t bf[2];
                bf[0] = *(const uint32_t*)&Vs[(ks * 8 + t) * VP + nt * 8 + g];
                bf[1] = *(const uint32_t*)&Vs[(ks * 8 + t + 4) * VP + nt * 8 + g];
                mma1688(o[nt], af, bf);
            }
        }
    }

    // ---- epilogue: normalize and store ----
    const float inv0 = 1.f / l0;
    const float inv1 = 1.f / l1;
#pragma unroll
    for (int nt = 0; nt < 8; nt++) {
        const size_t col = head_off + nt * 8 + 2 * t;
        float2 v0 = make_float2(o[nt][0] * inv0, o[nt][1] * inv0);
        float2 v1 = make_float2(o[nt][2] * inv1, o[nt][3] * inv1);
        *(float2*)(O + ((size_t)q_r0 * B_ + b) * D_ + col) = v0;
        *(float2*)(O + ((size_t)(q_r0 + 8) * B_ + b) * D_ + col) = v1;
    }
}

// ------------------------------------------------------------------
// Fused residual add + LayerNorm over D=1024 (unchanged).
// ------------------------------------------------------------------
__global__ __launch_bounds__(256) void add_ln_kernel(
    const float* __restrict__ a, const float* __restrict__ res,
    const float* __restrict__ g, const float* __restrict__ be,
    float* __restrict__ out)
{
    const size_t row = blockIdx.x;
    const float* pa = a + row * D_;
    const float* pr = res + row * D_;
    const int tid = threadIdx.x;

    float v[4];
    float s = 0.f, ss = 0.f;
#pragma unroll
    for (int i = 0; i < 4; i++) {
        const int c = tid + i * 256;
        const float x = pa[c] + pr[c];
        v[i] = x;
        s += x;
        ss += x * x;
    }
    __shared__ float red[2][8];
#pragma unroll
    for (int o = 16; o; o >>= 1) {
        s  += __shfl_xor_sync(0xffffffffu, s, o);
        ss += __shfl_xor_sync(0xffffffffu, ss, o);
    }
    const int w = tid >> 5;
    if ((tid & 31) == 0) { red[0][w] = s; red[1][w] = ss; }
    __syncthreads();
    if (tid < 32) {
        s  = (tid < 8) ? red[0][tid] : 0.f;
        ss = (tid < 8) ? red[1][tid] : 0.f;
#pragma unroll
        for (int o = 4; o; o >>= 1) {
            s  += __shfl_xor_sync(0xffffffffu, s, o);
            ss += __shfl_xor_sync(0xffffffffu, ss, o);
        }
        if (tid == 0) { red[0][0] = s; red[1][0] = ss; }
    }
    __syncthreads();
    s = red[0][0]; ss = red[1][0];

    const float mean = s * (1.f / 1024.f);
    const float var  = ss * (1.f / 1024.f) - mean * mean;
    const float rstd = rsqrtf(var + 1e-5f);
#pragma unroll
    for (int i = 0; i < 4; i++) {
        const int c = tid + i * 256;
        out[row * D_ + c] = (v[i] - mean) * rstd * g[c] + be[c];
    }
}

// ------------------------------------------------------------------
// Orchestration
// ------------------------------------------------------------------
extern "C" void kernel_launch(void* const* d_in, const int* in_sizes, int n_in,
                              void* d_out, int out_size)
{
    const float* enc = (const float*)d_in[0];
    const float* dec = (const float*)d_in[1];
    const float* Wq1 = (const float*)d_in[2];  const float* bq1 = (const float*)d_in[3];
    const float* Wk1 = (const float*)d_in[4];  const float* bk1 = (const float*)d_in[5];
    const float* Wv1 = (const float*)d_in[6];  const float* bv1 = (const float*)d_in[7];
    const float* Wq2 = (const float*)d_in[8];  const float* bq2 = (const float*)d_in[9];
    const float* Wk2 = (const float*)d_in[10]; const float* bk2 = (const float*)d_in[11];
    const float* Wv2 = (const float*)d_in[12]; const float* bv2 = (const float*)d_in[13];
    const float* Wl  = (const float*)d_in[14]; const float* bl  = (const float*)d_in[15];
    const float* g1  = (const float*)d_in[16]; const float* be1 = (const float*)d_in[17];
    const float* g2  = (const float*)d_in[18]; const float* be2 = (const float*)d_in[19];
    const float* g3  = (const float*)d_in[20]; const float* be3 = (const float*)d_in[21];
    float* out = (float*)d_out;

    float *q, *k, *v, *t, *x, *y;
    cudaGetSymbolAddress((void**)&q, g_q);
    cudaGetSymbolAddress((void**)&k, g_k);
    cudaGetSymbolAddress((void**)&v, g_v);
    cudaGetSymbolAddress((void**)&t, g_t);
    cudaGetSymbolAddress((void**)&x, g_x);
    cudaGetSymbolAddress((void**)&y, g_y);

    cudaFuncSetAttribute(attn_mma_kernel,
                         cudaFuncAttributeMaxDynamicSharedMemorySize, ATTN_SMEM);

    const dim3 gg(D_ / 128, M_ / 128);      // (8, 64)
    const dim3 ga(T_ / 128, B_ * H_);       // (8, 128)

    // --- self-attention block ---
    gemm_mma_kernel<<<gg, 256>>>(dec, Wq1, bq1, q);
    gemm_mma_kernel<<<gg, 256>>>(dec, Wk1, bk1, k);
    gemm_mma_kernel<<<gg, 256>>>(dec, Wv1, bv1, v);
    attn_mma_kernel<<<ga, 256, ATTN_SMEM>>>(q, k, v, t, 1);
    add_ln_kernel<<<M_, 256>>>(t, dec, g1, be1, x);

    // --- cross-attention block ---
    gemm_mma_kernel<<<gg, 256>>>(x,   Wq2, bq2, q);
    gemm_mma_kernel<<<gg, 256>>>(enc, Wk2, bk2, k);
    gemm_mma_kernel<<<gg, 256>>>(enc, Wv2, bv2, v);
    attn_mma_kernel<<<ga, 256, ATTN_SMEM>>>(q, k, v, t, 0);
    add_ln_kernel<<<M_, 256>>>(t, x, g2, be2, y);

    // --- position-wise linear + final LN ---
    gemm_mma_kernel<<<gg, 256>>>(y, Wl, bl, t);
    add_ln_kernel<<<M_, 256>>>(t, y, g3, be3, out);
}

// round 6
// speedup vs baseline: 5.2776x; 1.0401x over previous
#include <cuda_runtime.h>
#include <cstdint>

// Problem constants
#define T_  1024
#define B_  8
#define D_  1024
#define H_  16
#define NH_ 64
#define M_  (T_ * B_)   // 8192 token rows

// ------------------------------------------------------------------
// Scratch (static __device__ globals: allocation-free per harness rules)
// ------------------------------------------------------------------
__device__ float g_q[M_ * D_];
__device__ float g_k[M_ * D_];
__device__ float g_v[M_ * D_];
__device__ float g_t[M_ * D_];
__device__ float g_x[M_ * D_];
__device__ float g_y[M_ * D_];

// ------------------------------------------------------------------
// tf32 helpers
// ------------------------------------------------------------------
__device__ __forceinline__ uint32_t to_tf32(float x) {
    uint32_t r;
    asm("cvt.rna.tf32.f32 %0, %1;" : "=r"(r) : "f"(x));
    return r;
}

__device__ __forceinline__ void mma1688(float* c, const uint32_t* a,
                                        const uint32_t* b) {
    asm volatile(
        "mma.sync.aligned.m16n8k8.row.col.f32.tf32.tf32.f32 "
        "{%0,%1,%2,%3}, {%4,%5,%6,%7}, {%8,%9}, {%0,%1,%2,%3};\n"
        : "+f"(c[0]), "+f"(c[1]), "+f"(c[2]), "+f"(c[3])
        : "r"(a[0]), "r"(a[1]), "r"(a[2]), "r"(a[3]),
          "r"(b[0]), "r"(b[1]));
}

// ==================================================================
// tf32 mma.sync GEMM v2: double-buffered smem + register prefetch,
// one __syncthreads per k-block. Batched: grid.z picks a {W,bias,C}
// job sharing the same A (QKV projections fused into one launch).
// ==================================================================
#define GPITCH 36
#define GTILE  (128 * GPITCH)                      // floats per tile
#define GEMM_SMEM (2 * 2 * GTILE * 4)              // 73728 bytes

struct GemmJob  { const float* W; const float* bias; float* C; };
struct GemmJobs { GemmJob j[3]; };

__global__ __launch_bounds__(256, 2) void gemm_mma_kernel(
    const float* __restrict__ A, GemmJobs jobs)
{
    extern __shared__ float gsm[];
    float* As = gsm;                 // [2][128][GPITCH]
    float* Bs = gsm + 2 * GTILE;     // [2][128][GPITCH]

    const GemmJob jb = jobs.j[blockIdx.z];
    const float* __restrict__ W = jb.W;

    const int tid = threadIdx.x;
    const int wid = tid >> 5;
    const int lid = tid & 31;
    const int g   = lid >> 2;
    const int t   = lid & 3;

    const int warp_m = wid >> 1;
    const int warp_n = wid & 1;

    const int bn = blockIdx.x * 128;
    const int bm = blockIdx.y * 128;

    const int a_row0 = tid >> 3;
    const int a_c    = (tid & 7) * 4;
    const int b_n    = tid & 127;
    const int b_g0   = tid >> 7;

    float acc[2][8][4];
#pragma unroll
    for (int mt = 0; mt < 2; mt++)
#pragma unroll
        for (int nt = 0; nt < 8; nt++)
#pragma unroll
            for (int r = 0; r < 4; r++) acc[mt][nt][r] = 0.f;

    float4 pa[4], pb[4];

    // ---- prologue: load k-block 0 into regs, stage into buffer 0 ----
#pragma unroll
    for (int i = 0; i < 4; i++)
        pa[i] = *(const float4*)(A + (size_t)(bm + a_row0 + i * 32) * 1024 + a_c);
#pragma unroll
    for (int p = 0; p < 4; p++) {
        const int kk0 = (b_g0 + p * 2) * 4;
        const float* wp = W + (size_t)kk0 * 1024 + bn + b_n;
        pb[p] = make_float4(wp[0], wp[1024], wp[2048], wp[3072]);
    }
#pragma unroll
    for (int i = 0; i < 4; i++) {
        uint4 tv;
        tv.x = to_tf32(pa[i].x); tv.y = to_tf32(pa[i].y);
        tv.z = to_tf32(pa[i].z); tv.w = to_tf32(pa[i].w);
        *(uint4*)&As[(a_row0 + i * 32) * GPITCH + a_c] = tv;
    }
#pragma unroll
    for (int p = 0; p < 4; p++) {
        const int kk0 = (b_g0 + p * 2) * 4;
        uint4 tv;
        tv.x = to_tf32(pb[p].x); tv.y = to_tf32(pb[p].y);
        tv.z = to_tf32(pb[p].z); tv.w = to_tf32(pb[p].w);
        *(uint4*)&Bs[b_n * GPITCH + kk0] = tv;
    }
    __syncthreads();

    for (int kb = 0; kb < 32; kb++) {
        const int buf = kb & 1;
        const float* curA = As + buf * GTILE;
        const float* curB = Bs + buf * GTILE;

        // ---- issue next k-block's global loads (latency hidden by MMAs) ----
        if (kb < 31) {
            const int k1 = (kb + 1) * 32;
#pragma unroll
            for (int i = 0; i < 4; i++)
                pa[i] = *(const float4*)(A + (size_t)(bm + a_row0 + i * 32) * 1024
                                         + k1 + a_c);
#pragma unroll
            for (int p = 0; p < 4; p++) {
                const int kk0 = (b_g0 + p * 2) * 4;
                const float* wp = W + (size_t)(k1 + kk0) * 1024 + bn + b_n;
                pb[p] = make_float4(wp[0], wp[1024], wp[2048], wp[3072]);
            }
        }

        // ---- compute current buffer: 4 k-steps x (2m x 8n) MMAs ----
#pragma unroll
        for (int ks = 0; ks < 4; ks++) {
            uint32_t af[2][4];
#pragma unroll
            for (int mt = 0; mt < 2; mt++) {
                const uint32_t* ap = (const uint32_t*)
                    &curA[(warp_m * 32 + mt * 16 + g) * GPITCH + ks * 8 + t];
                af[mt][0] = ap[0];
                af[mt][1] = ap[8 * GPITCH];
                af[mt][2] = ap[4];
                af[mt][3] = ap[8 * GPITCH + 4];
            }
#pragma unroll
            for (int nt = 0; nt < 8; nt++) {
                const uint32_t* bp = (const uint32_t*)
                    &curB[(warp_n * 64 + nt * 8 + g) * GPITCH + ks * 8 + t];
                uint32_t bf[2] = {bp[0], bp[4]};
                mma1688(acc[0][nt], af[0], bf);
                mma1688(acc[1][nt], af[1], bf);
            }
        }

        // ---- stage next k-block into the other buffer ----
        if (kb < 31) {
            float* nxtA = As + (buf ^ 1) * GTILE;
            float* nxtB = Bs + (buf ^ 1) * GTILE;
#pragma unroll
            for (int i = 0; i < 4; i++) {
                uint4 tv;
                tv.x = to_tf32(pa[i].x); tv.y = to_tf32(pa[i].y);
                tv.z = to_tf32(pa[i].z); tv.w = to_tf32(pa[i].w);
                *(uint4*)&nxtA[(a_row0 + i * 32) * GPITCH + a_c] = tv;
            }
#pragma unroll
            for (int p = 0; p < 4; p++) {
                const int kk0 = (b_g0 + p * 2) * 4;
                uint4 tv;
                tv.x = to_tf32(pb[p].x); tv.y = to_tf32(pb[p].y);
                tv.z = to_tf32(pb[p].z); tv.w = to_tf32(pb[p].w);
                *(uint4*)&nxtB[b_n * GPITCH + kk0] = tv;
            }
        }
        __syncthreads();
    }

    // ---- epilogue: bias + store ----
#pragma unroll
    for (int nt = 0; nt < 8; nt++) {
        const int col = bn + warp_n * 64 + nt * 8 + 2 * t;
        const float2 bv = *(const float2*)(jb.bias + col);
#pragma unroll
        for (int mt = 0; mt < 2; mt++) {
            const int row0 = bm + warp_m * 32 + mt * 16 + g;
            float2 v0 = make_float2(acc[mt][nt][0] + bv.x,
                                    acc[mt][nt][1] + bv.y);
            float2 v1 = make_float2(acc[mt][nt][2] + bv.x,
                                    acc[mt][nt][3] + bv.y);
            *(float2*)(jb.C + (size_t)row0 * 1024 + col) = v0;
            *(float2*)(jb.C + (size_t)(row0 + 8) * 1024 + col) = v1;
        }
    }
}

// ==================================================================
// FlashAttention-2-style tf32 mma.sync attention (unchanged from R5).
// ==================================================================
#define QP 68
#define KP 68
#define VP 72
#define PP 68
#define ATTN_SMEM ((128 * QP + 64 * KP + 64 * VP + 128 * PP) * 4)  // 105472 B

__global__ __launch_bounds__(256, 2) void attn_mma_kernel(
    const float* __restrict__ Q, const float* __restrict__ K,
    const float* __restrict__ V, float* __restrict__ O, int causal)
{
    extern __shared__ float sm[];
    float* Qs = sm;                      // [128][QP]
    float* Ks = Qs + 128 * QP;           // [64][KP]
    float* Vs = Ks + 64 * KP;            // [64][VP]
    float* Ps = Vs + 64 * VP;            // [128][PP]

    const int qt  = blockIdx.x;
    const int bh  = blockIdx.y;
    const int b   = bh >> 4;
    const int h   = bh & 15;
    const int tid = threadIdx.x;
    const int wid = tid >> 5;
    const int lid = tid & 31;
    const int g   = lid >> 2;
    const int t   = lid & 3;

    const size_t head_off = (size_t)h * NH_;
    const int lr = tid >> 2;
    const int lc = (tid & 3) * 16;

#pragma unroll
    for (int half = 0; half < 2; half++) {
        const int row = lr + half * 64;
        const float* src = Q + ((size_t)(qt * 128 + row) * B_ + b) * D_
                             + head_off + lc;
#pragma unroll
        for (int j = 0; j < 16; j += 4) {
            const float4 v = *(const float4*)(src + j);
            uint4 tv;
            tv.x = to_tf32(v.x); tv.y = to_tf32(v.y);
            tv.z = to_tf32(v.z); tv.w = to_tf32(v.w);
            *(uint4*)&Qs[row * QP + lc + j] = tv;
        }
    }

    float m0 = -INFINITY, m1 = -INFINITY, l0 = 0.f, l1 = 0.f;
    float o[8][4];
#pragma unroll
    for (int nt = 0; nt < 8; nt++)
#pragma unroll
        for (int r = 0; r < 4; r++) o[nt][r] = 0.f;

    const int nkt = causal ? (2 * qt + 2) : (T_ / 64);
    const int q_r0 = qt * 128 + wid * 16 + g;
    const int qrow_s = wid * 16 + g;

    for (int kt = 0; kt < nkt; kt++) {
        __syncthreads();

        {
            const float* ksrc = K + ((size_t)(kt * 64 + lr) * B_ + b) * D_
                                  + head_off + lc;
            const float* vsrc = V + ((size_t)(kt * 64 + lr) * B_ + b) * D_
                                  + head_off + lc;
#pragma unroll
            for (int j = 0; j < 16; j += 4) {
                const float4 kv = *(const float4*)(ksrc + j);
                uint4 tk;
                tk.x = to_tf32(kv.x); tk.y = to_tf32(kv.y);
                tk.z = to_tf32(kv.z); tk.w = to_tf32(kv.w);
                *(uint4*)&Ks[lr * KP + lc + j] = tk;
                const float4 vv = *(const float4*)(vsrc + j);
                uint4 tv;
                tv.x = to_tf32(vv.x); tv.y = to_tf32(vv.y);
                tv.z = to_tf32(vv.z); tv.w = to_tf32(vv.w);
                *(uint4*)&Vs[lr * VP + lc + j] = tv;
            }
        }
        __syncthreads();

        float sacc[8][4];
#pragma unroll
        for (int nt = 0; nt < 8; nt++)
#pragma unroll
            for (int r = 0; r < 4; r++) sacc[nt][r] = 0.f;

#pragma unroll
        for (int ks = 0; ks < 8; ks++) {
            uint32_t af[4];
            const uint32_t* ap = (const uint32_t*)&Qs[qrow_s * QP + ks * 8 + t];
            af[0] = ap[0];
            af[1] = ap[8 * QP];
            af[2] = ap[4];
            af[3] = ap[8 * QP + 4];
#pragma unroll
            for (int nt = 0; nt < 8; nt++) {
                const uint32_t* bp =
                    (const uint32_t*)&Ks[(nt * 8 + g) * KP + ks * 8 + t];
                uint32_t bf[2] = {bp[0], bp[4]};
                mma1688(sacc[nt], af, bf);
            }
        }

        const float scale = 0.125f;
        const bool domask = causal && (kt >= 2 * qt);
        float rmax0 = -INFINITY, rmax1 = -INFINITY;
#pragma unroll
        for (int nt = 0; nt < 8; nt++) {
            float c0 = sacc[nt][0] * scale;
            float c1 = sacc[nt][1] * scale;
            float c2 = sacc[nt][2] * scale;
            float c3 = sacc[nt][3] * scale;
            if (domask) {
                const int col = kt * 64 + nt * 8 + 2 * t;
                if (col     > q_r0)     c0 = -INFINITY;
                if (col + 1 > q_r0)     c1 = -INFINITY;
                if (col     > q_r0 + 8) c2 = -INFINITY;
                if (col + 1 > q_r0 + 8) c3 = -INFINITY;
            }
            sacc[nt][0] = c0; sacc[nt][1] = c1;
            sacc[nt][2] = c2; sacc[nt][3] = c3;
            rmax0 = fmaxf(rmax0, fmaxf(c0, c1));
            rmax1 = fmaxf(rmax1, fmaxf(c2, c3));
        }
        rmax0 = fmaxf(rmax0, __shfl_xor_sync(0xffffffffu, rmax0, 1));
        rmax0 = fmaxf(rmax0, __shfl_xor_sync(0xffffffffu, rmax0, 2));
        rmax1 = fmaxf(rmax1, __shfl_xor_sync(0xffffffffu, rmax1, 1));
        rmax1 = fmaxf(rmax1, __shfl_xor_sync(0xffffffffu, rmax1, 2));

        const float mn0 = fmaxf(m0, rmax0);
        const float mn1 = fmaxf(m1, rmax1);
        const float corr0 = __expf(m0 - mn0);
        const float corr1 = __expf(m1 - mn1);

        float ps0 = 0.f, ps1 = 0.f;
#pragma unroll
        for (int nt = 0; nt < 8; nt++) {
            const float p0 = __expf(sacc[nt][0] - mn0);
            const float p1 = __expf(sacc[nt][1] - mn0);
            const float p2 = __expf(sacc[nt][2] - mn1);
            const float p3 = __expf(sacc[nt][3] - mn1);
            ps0 += p0 + p1;
            ps1 += p2 + p3;
            float2 w0, w1;
            w0.x = __uint_as_float(to_tf32(p0));
            w0.y = __uint_as_float(to_tf32(p1));
            w1.x = __uint_as_float(to_tf32(p2));
            w1.y = __uint_as_float(to_tf32(p3));
            *(float2*)&Ps[qrow_s * PP + nt * 8 + 2 * t] = w0;
            *(float2*)&Ps[(qrow_s + 8) * PP + nt * 8 + 2 * t] = w1;
        }
        ps0 += __shfl_xor_sync(0xffffffffu, ps0, 1);
        ps0 += __shfl_xor_sync(0xffffffffu, ps0, 2);
        ps1 += __shfl_xor_sync(0xffffffffu, ps1, 1);
        ps1 += __shfl_xor_sync(0xffffffffu, ps1, 2);

        l0 = l0 * corr0 + ps0;
        l1 = l1 * corr1 + ps1;
        m0 = mn0;
        m1 = mn1;
#pragma unroll
        for (int nt = 0; nt < 8; nt++) {
            o[nt][0] *= corr0; o[nt][1] *= corr0;
            o[nt][2] *= corr1; o[nt][3] *= corr1;
        }

        __syncwarp();

#pragma unroll
        for (int ks = 0; ks < 8; ks++) {
            uint32_t af[4];
            const uint32_t* ap = (const uint32_t*)&Ps[qrow_s * PP + ks * 8 + t];
            af[0] = ap[0];
            af[1] = ap[8 * PP];
            af[2] = ap[4];
            af[3] = ap[8 * PP + 4];
#pragma unroll
            for (int nt = 0; nt < 8; nt++) {
                uint32_t bf[2];
                bf[0] = *(const uint32_t*)&Vs[(ks * 8 + t) * VP + nt * 8 + g];
                bf[1] = *(const uint32_t*)&Vs[(ks * 8 + t + 4) * VP + nt * 8 + g];
                mma1688(o[nt], af, bf);
            }
        }
    }

    const float inv0 = 1.f / l0;
    const float inv1 = 1.f / l1;
#pragma unroll
    for (int nt = 0; nt < 8; nt++) {
        const size_t col = head_off + nt * 8 + 2 * t;
        float2 v0 = make_float2(o[nt][0] * inv0, o[nt][1] * inv0);
        float2 v1 = make_float2(o[nt][2] * inv1, o[nt][3] * inv1);
        *(float2*)(O + ((size_t)q_r0 * B_ + b) * D_ + col) = v0;
        *(float2*)(O + ((size_t)(q_r0 + 8) * B_ + b) * D_ + col) = v1;
    }
}

// ------------------------------------------------------------------
// Fused residual add + LayerNorm over D=1024 (unchanged).
// ------------------------------------------------------------------
__global__ __launch_bounds__(256) void add_ln_kernel(
    const float* __restrict__ a, const float* __restrict__ res,
    const float* __restrict__ g, const float* __restrict__ be,
    float* __restrict__ out)
{
    const size_t row = blockIdx.x;
    const float* pa = a + row * D_;
    const float* pr = res + row * D_;
    const int tid = threadIdx.x;

    float v[4];
    float s = 0.f, ss = 0.f;
#pragma unroll
    for (int i = 0; i < 4; i++) {
        const int c = tid + i * 256;
        const float x = pa[c] + pr[c];
        v[i] = x;
        s += x;
        ss += x * x;
    }
    __shared__ float red[2][8];
#pragma unroll
    for (int o = 16; o; o >>= 1) {
        s  += __shfl_xor_sync(0xffffffffu, s, o);
        ss += __shfl_xor_sync(0xffffffffu, ss, o);
    }
    const int w = tid >> 5;
    if ((tid & 31) == 0) { red[0][w] = s; red[1][w] = ss; }
    __syncthreads();
    if (tid < 32) {
        s  = (tid < 8) ? red[0][tid] : 0.f;
        ss = (tid < 8) ? red[1][tid] : 0.f;
#pragma unroll
        for (int o = 4; o; o >>= 1) {
            s  += __shfl_xor_sync(0xffffffffu, s, o);
            ss += __shfl_xor_sync(0xffffffffu, ss, o);
        }
        if (tid == 0) { red[0][0] = s; red[1][0] = ss; }
    }
    __syncthreads();
    s = red[0][0]; ss = red[1][0];

    const float mean = s * (1.f / 1024.f);
    const float var  = ss * (1.f / 1024.f) - mean * mean;
    const float rstd = rsqrtf(var + 1e-5f);
#pragma unroll
    for (int i = 0; i < 4; i++) {
        const int c = tid + i * 256;
        out[row * D_ + c] = (v[i] - mean) * rstd * g[c] + be[c];
    }
}

// ------------------------------------------------------------------
// Orchestration
// ------------------------------------------------------------------
extern "C" void kernel_launch(void* const* d_in, const int* in_sizes, int n_in,
                              void* d_out, int out_size)
{
    const float* enc = (const float*)d_in[0];
    const float* dec = (const float*)d_in[1];
    const float* Wq1 = (const float*)d_in[2];  const float* bq1 = (const float*)d_in[3];
    const float* Wk1 = (const float*)d_in[4];  const float* bk1 = (const float*)d_in[5];
    const float* Wv1 = (const float*)d_in[6];  const float* bv1 = (const float*)d_in[7];
    const float* Wq2 = (const float*)d_in[8];  const float* bq2 = (const float*)d_in[9];
    const float* Wk2 = (const float*)d_in[10]; const float* bk2 = (const float*)d_in[11];
    const float* Wv2 = (const float*)d_in[12]; const float* bv2 = (const float*)d_in[13];
    const float* Wl  = (const float*)d_in[14]; const float* bl  = (const float*)d_in[15];
    const float* g1  = (const float*)d_in[16]; const float* be1 = (const float*)d_in[17];
    const float* g2  = (const float*)d_in[18]; const float* be2 = (const float*)d_in[19];
    const float* g3  = (const float*)d_in[20]; const float* be3 = (const float*)d_in[21];
    float* out = (float*)d_out;

    float *q, *k, *v, *t, *x, *y;
    cudaGetSymbolAddress((void**)&q, g_q);
    cudaGetSymbolAddress((void**)&k, g_k);
    cudaGetSymbolAddress((void**)&v, g_v);
    cudaGetSymbolAddress((void**)&t, g_t);
    cudaGetSymbolAddress((void**)&x, g_x);
    cudaGetSymbolAddress((void**)&y, g_y);

    cudaFuncSetAttribute(attn_mma_kernel,
                         cudaFuncAttributeMaxDynamicSharedMemorySize, ATTN_SMEM);
    cudaFuncSetAttribute(gemm_mma_kernel,
                         cudaFuncAttributeMaxDynamicSharedMemorySize, GEMM_SMEM);

    const dim3 ga(T_ / 128, B_ * H_);       // (8, 128)

    GemmJobs qkv1 = {{{Wq1, bq1, q}, {Wk1, bk1, k}, {Wv1, bv1, v}}};
    GemmJobs q2j  = {{{Wq2, bq2, q}, {Wq2, bq2, q}, {Wq2, bq2, q}}};
    GemmJobs kv2  = {{{Wk2, bk2, k}, {Wv2, bv2, v}, {Wv2, bv2, v}}};
    GemmJobs lin  = {{{Wl,  bl,  t}, {Wl,  bl,  t}, {Wl,  bl,  t}}};

    // --- self-attention block ---
    gemm_mma_kernel<<<dim3(8, 64, 3), 256, GEMM_SMEM>>>(dec, qkv1);
    attn_mma_kernel<<<ga, 256, ATTN_SMEM>>>(q, k, v, t, 1);
    add_ln_kernel<<<M_, 256>>>(t, dec, g1, be1, x);

    // --- cross-attention block ---
    gemm_mma_kernel<<<dim3(8, 64, 2), 256, GEMM_SMEM>>>(enc, kv2);
    gemm_mma_kernel<<<dim3(8, 64, 1), 256, GEMM_SMEM>>>(x, q2j);
    attn_mma_kernel<<<ga, 256, ATTN_SMEM>>>(q, k, v, t, 0);
    add_ln_kernel<<<M_, 256>>>(t, x, g2, be2, y);

    // --- position-wise linear + final LN ---
    gemm_mma_kernel<<<dim3(8, 64, 1), 256, GEMM_SMEM>>>(y, lin);
    add_ln_kernel<<<M_, 256>>>(t, y, g3, be3, out);
}